// round 10
// baseline (speedup 1.0000x reference)
#include <cuda_runtime.h>
#include <cuda_fp16.h>

#define N_NODES 100000
#define N_EDGES 3200000
#define F_IN 128
#define F_H 32
#define CAP 128                              // bucket capacity (P(deg>=128) ~ 1e-40)

#define H1_BLOCKS  (N_NODES / 32)            // 3125: 32 rows per block
#define CSR_BLOCKS (N_EDGES / 256)           // 12500
#define FUSED_BLOCKS (H1_BLOCKS + CSR_BLOCKS)

// ---------------- scratch (static device globals; no allocation) ----------------
__device__ int    g_is64;                    // edge_index dtype flag
__device__ int    g_cursor[N_NODES];         // real in-degree (excl. self loop)
__device__ float  g_dinv[N_NODES];           // (deg+1)^{-1/2}
__device__ int    g_rows[N_NODES * CAP];     // padded CSR: sources for node c at c*CAP
__device__ __align__(16) float  g_h1[N_NODES * F_H];    // RAW x @ W1 (fp32)
__device__ __align__(16) __half g_h1h[N_NODES * F_H];   // dinv[r] * h1[r], fp16
__device__ float4 g_h2[N_NODES];             // dinv[c] * (tanh(agg1) @ W2)[c], padded

// ---------------- kernels ----------------

// zero cursors; thread 0 detects int32 vs int64 edge_index
// (int64 values < 2^31 have all odd 32-bit words == 0; random int32 essentially never does)
__global__ void k_init(const int* __restrict__ ei_words) {
    int i = blockIdx.x * blockDim.x + threadIdx.x;
    if (i < N_NODES) g_cursor[i] = 0;
    if (i == 0) {
        int all_odd_zero = 1;
        for (int w = 1; w < 16; w += 2)
            if (ei_words[w] != 0) all_odd_zero = 0;
        g_is64 = all_odd_zero;
    }
}

// FUSED: blocks [0, H1_BLOCKS) do raw h1 = x @ W1 (smem-tiled, thread tiling);
// blocks [H1_BLOCKS, ...) do the one-pass padded-CSR build.
__global__ void __launch_bounds__(256) k_fused(const float* __restrict__ x,
                                               const float* __restrict__ W1,
                                               const void* __restrict__ ei) {
    if (blockIdx.x < H1_BLOCKS) {
        // ---- GEMM: block computes rows [b*32, b*32+32) x all 32 cols.
        __shared__ float sx[32 * F_IN];        // 16 KB, x tile (row-major)
        __shared__ float sWT[F_H * (F_IN + 4)];// 16.9 KB, W1 transposed: sWT[col][k]
        int tid = threadIdx.x;
        int row0 = blockIdx.x * 32;

        const float4* x4 = (const float4*)(x + (size_t)row0 * F_IN);
        float4* sx4 = (float4*)sx;
#pragma unroll
        for (int i = 0; i < 4; i++)
            sx4[i * 256 + tid] = x4[i * 256 + tid];

#pragma unroll
        for (int i = 0; i < 16; i++) {
            int idx = i * 256 + tid;           // 0..4095
            int k = idx >> 5, col = idx & 31;
            sWT[col * (F_IN + 4) + k] = W1[idx];
        }
        __syncthreads();

        int warp = tid >> 5, lane = tid & 31;  // warp handles 4 rows, lane = out col
        int r0 = warp * 4;
        const float4* wt4 = (const float4*)(sWT + lane * (F_IN + 4));
        const float4* xr0 = (const float4*)(sx + (r0 + 0) * F_IN);
        const float4* xr1 = (const float4*)(sx + (r0 + 1) * F_IN);
        const float4* xr2 = (const float4*)(sx + (r0 + 2) * F_IN);
        const float4* xr3 = (const float4*)(sx + (r0 + 3) * F_IN);
        float a0 = 0.f, a1 = 0.f, a2 = 0.f, a3 = 0.f;
#pragma unroll
        for (int k4 = 0; k4 < 32; k4++) {
            float4 wv = wt4[k4];
            float4 v0 = xr0[k4];
            float4 v1 = xr1[k4];
            float4 v2 = xr2[k4];
            float4 v3 = xr3[k4];
            a0 += v0.x * wv.x + v0.y * wv.y + v0.z * wv.z + v0.w * wv.w;
            a1 += v1.x * wv.x + v1.y * wv.y + v1.z * wv.z + v1.w * wv.w;
            a2 += v2.x * wv.x + v2.y * wv.y + v2.z * wv.z + v2.w * wv.w;
            a3 += v3.x * wv.x + v3.y * wv.y + v3.z * wv.z + v3.w * wv.w;
        }
        int ob = (row0 + r0) * F_H + lane;
        g_h1[ob + 0 * F_H] = a0;
        g_h1[ob + 1 * F_H] = a1;
        g_h1[ob + 2 * F_H] = a2;
        g_h1[ob + 3 * F_H] = a3;
    } else {
        // ---- CSR part: one edge per thread, one-pass bucket scatter
        int e = (blockIdx.x - H1_BLOCKS) * 256 + threadIdx.x;   // always < N_EDGES
        int r, c;
        if (g_is64) {
            r = (int)((const long long*)ei)[e];
            c = (int)((const long long*)ei)[N_EDGES + e];
        } else {
            r = ((const int*)ei)[e];
            c = ((const int*)ei)[N_EDGES + e];
        }
        int pos = atomicAdd(&g_cursor[c], 1);
        if (pos < CAP) g_rows[c * CAP + pos] = r;
    }
}

// dinv + fp16 scale: one warp per node; writes g_dinv and g_h1h = dinv*h1 (fp16)
__global__ void __launch_bounds__(256) k_dinvscale() {
    int node = (blockIdx.x * blockDim.x + threadIdx.x) >> 5;
    int lane = threadIdx.x & 31;
    if (node >= N_NODES) return;
    float d = rsqrtf((float)(g_cursor[node] + 1));
    if (lane == 0) g_dinv[node] = d;
    float v = g_h1[node * F_H + lane];
    g_h1h[node * F_H + lane] = __float2half_rn(d * v);
}

// Layer-1 aggregation: HALF-WARP per node. Lane = 16*half + p; lane covers
// feature pair p (half2) of its node. One warp instruction covers 2 edges
// (one per node). fp32 accumulation (no fp16 chains). Then tanh + fused 32->3.
__global__ void __launch_bounds__(256) k_agg1(const float* __restrict__ W2) {
    __shared__ float sW[F_H * 3];
    if (threadIdx.x < F_H * 3) sW[threadIdx.x] = W2[threadIdx.x];
    __syncthreads();
    const unsigned FULL = 0xffffffffu;
    int wg   = (blockIdx.x * blockDim.x + threadIdx.x) >> 5;   // warp id
    int lane = threadIdx.x & 31;
    int half = lane >> 4;
    int p    = lane & 15;                   // feature pair index (2p, 2p+1)
    int node = wg * 2 + half;               // N even -> whole warp valid or exits
    if (node >= N_NODES) return;

    int deg = g_cursor[node]; if (deg > CAP) deg = CAP;
    const int* rows = g_rows + node * CAP;
    float dn = g_dinv[node];
    const half2* h2p = (const half2*)g_h1h; // [N_NODES * 16]

    float2 self = __half22float2(h2p[node * 16 + p]);
    float ax = self.x, ay = self.y;         // fp32 accumulators

    int dmax = deg;
    dmax = max(dmax, __shfl_xor_sync(FULL, dmax, 16));
    int src = half << 4;                    // shfl source base for my half

    for (int base = 0; base < dmax; base += 16) {
        int idx = base + p;
        int myr = (idx < deg) ? rows[idx] : 0;   // lane p holds index of edge base+p
        if (base + 16 <= deg) {
            // fast path: all 16 edges valid, unroll 4 -> 4 loads in flight
#pragma unroll
            for (int j = 0; j < 16; j += 4) {
                int r0 = __shfl_sync(FULL, myr, src + j + 0);
                int r1 = __shfl_sync(FULL, myr, src + j + 1);
                int r2 = __shfl_sync(FULL, myr, src + j + 2);
                int r3 = __shfl_sync(FULL, myr, src + j + 3);
                float2 f0 = __half22float2(h2p[r0 * 16 + p]);
                float2 f1 = __half22float2(h2p[r1 * 16 + p]);
                float2 f2 = __half22float2(h2p[r2 * 16 + p]);
                float2 f3 = __half22float2(h2p[r3 * 16 + p]);
                ax += (f0.x + f1.x) + (f2.x + f3.x);
                ay += (f0.y + f1.y) + (f2.y + f3.y);
            }
        } else {
            // boundary chunk: per-edge guard with safe index
            for (int j = 0; j < 16; j++) {
                int r = __shfl_sync(FULL, myr, src + j);
                bool v = (base + j) < deg;
                r = v ? r : 0;
                float2 f = __half22float2(h2p[r * 16 + p]);
                if (v) { ax += f.x; ay += f.y; }
            }
        }
    }

    float a1x = tanhf(ax * dn);             // feature 2p
    float a1y = tanhf(ay * dn);             // feature 2p+1

    // fused projection within the half-warp: butterfly over 16 lanes
    float s0 = a1x * sW[(2 * p) * 3 + 0] + a1y * sW[(2 * p + 1) * 3 + 0];
    float s1 = a1x * sW[(2 * p) * 3 + 1] + a1y * sW[(2 * p + 1) * 3 + 1];
    float s2 = a1x * sW[(2 * p) * 3 + 2] + a1y * sW[(2 * p + 1) * 3 + 2];
#pragma unroll
    for (int d = 8; d > 0; d >>= 1) {
        s0 += __shfl_xor_sync(FULL, s0, d);
        s1 += __shfl_xor_sync(FULL, s1, d);
        s2 += __shfl_xor_sync(FULL, s2, d);
    }
    if (p == 0)
        g_h2[node] = make_float4(dn * s0, dn * s1, dn * s2, 0.f);
}

// Layer-2 aggregation: one warp per node, lanes stride over edges, warp reduce
__global__ void __launch_bounds__(256) k_agg2(float* __restrict__ out) {
    int node = (blockIdx.x * blockDim.x + threadIdx.x) >> 5;
    int lane = threadIdx.x & 31;
    if (node >= N_NODES) return;
    int deg = g_cursor[node]; if (deg > CAP) deg = CAP;
    const int* rows = g_rows + node * CAP;
    float s0 = 0.f, s1 = 0.f, s2 = 0.f;
    for (int e = lane; e < deg; e += 32) {
        float4 h = g_h2[rows[e]];
        s0 += h.x; s1 += h.y; s2 += h.z;
    }
#pragma unroll
    for (int d = 16; d > 0; d >>= 1) {
        s0 += __shfl_down_sync(0xffffffffu, s0, d);
        s1 += __shfl_down_sync(0xffffffffu, s1, d);
        s2 += __shfl_down_sync(0xffffffffu, s2, d);
    }
    if (lane == 0) {
        float dc = g_dinv[node];
        float4 h = g_h2[node];   // self loop (already dinv-scaled)
        out[node * 3 + 0] = dc * (s0 + h.x);
        out[node * 3 + 1] = dc * (s1 + h.y);
        out[node * 3 + 2] = dc * (s2 + h.z);
    }
}

// ---------------- launcher ----------------
extern "C" void kernel_launch(void* const* d_in, const int* in_sizes, int n_in,
                              void* d_out, int out_size) {
    const float* x  = (const float*)d_in[0];
    const void*  ei = d_in[1];                 // [2, E] int32 or int64 (runtime-detected)
    const float* W1 = (const float*)d_in[2];
    const float* W2 = (const float*)d_in[3];
    float* out = (float*)d_out;

    k_init<<<(N_NODES + 255) / 256, 256>>>((const int*)ei);
    k_fused<<<FUSED_BLOCKS, 256>>>(x, W1, ei);      // tiled GEMM + CSR build
    k_dinvscale<<<(N_NODES + 7) / 8, 256>>>();      // dinv + fp16 pre-scaled h1
    k_agg1<<<(N_NODES / 2 + 7) / 8, 256>>>(W2);     // HALF-warp per node, fused h2
    k_agg2<<<(N_NODES + 7) / 8, 256>>>(out);        // warp per node
}

// round 11
// speedup vs baseline: 1.1083x; 1.1083x over previous
#include <cuda_runtime.h>
#include <cuda_fp16.h>

#define N_NODES 100000
#define N_EDGES 3200000
#define F_IN 128
#define F_H 32
#define CAP 128                              // bucket capacity (P(deg>=128) ~ 1e-40)

#define H1_BLOCKS  (N_NODES / 32)            // 3125: 32 rows per block
#define CSR_BLOCKS (N_EDGES / 512)           // 6250: 2 edges per thread
#define FUSED_BLOCKS (H1_BLOCKS + CSR_BLOCKS)

// ---------------- scratch (static device globals; no allocation) ----------------
__device__ int    g_is64;                    // edge_index dtype flag
__device__ int    g_cursor[N_NODES];         // real in-degree (excl. self loop)
__device__ float  g_dinv[N_NODES];           // (deg+1)^{-1/2}
__device__ int    g_rows[N_NODES * CAP];     // padded CSR: sources for node c at c*CAP
__device__ __align__(16) float  g_h1[N_NODES * F_H];    // RAW x @ W1 (fp32)
__device__ __align__(16) __half g_h1h[N_NODES * F_H];   // dinv[r] * h1[r], fp16
__device__ float4 g_h2[N_NODES];             // dinv[c] * (tanh(agg1) @ W2)[c], padded

// ---------------- kernels ----------------

// zero cursors; thread 0 detects int32 vs int64 edge_index
// (int64 values < 2^31 have all odd 32-bit words == 0; random int32 essentially never does)
__global__ void k_init(const int* __restrict__ ei_words) {
    int i = blockIdx.x * blockDim.x + threadIdx.x;
    if (i < N_NODES) g_cursor[i] = 0;
    if (i == 0) {
        int all_odd_zero = 1;
        for (int w = 1; w < 16; w += 2)
            if (ei_words[w] != 0) all_odd_zero = 0;
        g_is64 = all_odd_zero;
    }
}

// FUSED: blocks [0, H1_BLOCKS) do raw h1 = x @ W1 (smem-tiled, thread tiling);
// blocks [H1_BLOCKS, ...) do the one-pass padded-CSR build, 2 edges/thread with
// vectorized edge loads (3 LSU ops/edge instead of 4 -> LSU-issue-bound kernel).
__global__ void __launch_bounds__(256) k_fused(const float* __restrict__ x,
                                               const float* __restrict__ W1,
                                               const void* __restrict__ ei) {
    if (blockIdx.x < H1_BLOCKS) {
        // ---- GEMM: block computes rows [b*32, b*32+32) x all 32 cols.
        __shared__ float sx[32 * F_IN];        // 16 KB, x tile (row-major)
        __shared__ float sWT[F_H * (F_IN + 4)];// 16.9 KB, W1 transposed: sWT[col][k]
        int tid = threadIdx.x;
        int row0 = blockIdx.x * 32;

        const float4* x4 = (const float4*)(x + (size_t)row0 * F_IN);
        float4* sx4 = (float4*)sx;
#pragma unroll
        for (int i = 0; i < 4; i++)
            sx4[i * 256 + tid] = x4[i * 256 + tid];

#pragma unroll
        for (int i = 0; i < 16; i++) {
            int idx = i * 256 + tid;           // 0..4095
            int k = idx >> 5, col = idx & 31;
            sWT[col * (F_IN + 4) + k] = W1[idx];
        }
        __syncthreads();

        int warp = tid >> 5, lane = tid & 31;  // warp handles 4 rows, lane = out col
        int r0 = warp * 4;
        const float4* wt4 = (const float4*)(sWT + lane * (F_IN + 4));
        const float4* xr0 = (const float4*)(sx + (r0 + 0) * F_IN);
        const float4* xr1 = (const float4*)(sx + (r0 + 1) * F_IN);
        const float4* xr2 = (const float4*)(sx + (r0 + 2) * F_IN);
        const float4* xr3 = (const float4*)(sx + (r0 + 3) * F_IN);
        float a0 = 0.f, a1 = 0.f, a2 = 0.f, a3 = 0.f;
#pragma unroll
        for (int k4 = 0; k4 < 32; k4++) {
            float4 wv = wt4[k4];
            float4 v0 = xr0[k4];
            float4 v1 = xr1[k4];
            float4 v2 = xr2[k4];
            float4 v3 = xr3[k4];
            a0 += v0.x * wv.x + v0.y * wv.y + v0.z * wv.z + v0.w * wv.w;
            a1 += v1.x * wv.x + v1.y * wv.y + v1.z * wv.z + v1.w * wv.w;
            a2 += v2.x * wv.x + v2.y * wv.y + v2.z * wv.z + v2.w * wv.w;
            a3 += v3.x * wv.x + v3.y * wv.y + v3.z * wv.z + v3.w * wv.w;
        }
        int ob = (row0 + r0) * F_H + lane;
        g_h1[ob + 0 * F_H] = a0;
        g_h1[ob + 1 * F_H] = a1;
        g_h1[ob + 2 * F_H] = a2;
        g_h1[ob + 3 * F_H] = a3;
    } else {
        // ---- CSR part: 2 edges per thread, vectorized loads
        int t = (blockIdx.x - H1_BLOCKS) * 256 + threadIdx.x;   // < N_EDGES/2
        int r0, r1, c0, c1;
        if (g_is64) {
            const longlong2* pr = (const longlong2*)ei;
            const longlong2* pc = (const longlong2*)((const long long*)ei + N_EDGES);
            longlong2 r = pr[t], c = pc[t];
            r0 = (int)r.x; r1 = (int)r.y; c0 = (int)c.x; c1 = (int)c.y;
        } else {
            const int2* pr = (const int2*)ei;
            const int2* pc = (const int2*)((const int*)ei + N_EDGES);
            int2 r = pr[t], c = pc[t];
            r0 = r.x; r1 = r.y; c0 = c.x; c1 = c.y;
        }
        int p0 = atomicAdd(&g_cursor[c0], 1);
        if (p0 < CAP) g_rows[c0 * CAP + p0] = r0;
        int p1 = atomicAdd(&g_cursor[c1], 1);
        if (p1 < CAP) g_rows[c1 * CAP + p1] = r1;
    }
}

// dinv + fp16 scale: one warp per node; writes g_dinv and g_h1h = dinv*h1 (fp16)
__global__ void __launch_bounds__(256) k_dinvscale() {
    int node = (blockIdx.x * blockDim.x + threadIdx.x) >> 5;
    int lane = threadIdx.x & 31;
    if (node >= N_NODES) return;
    float d = rsqrtf((float)(g_cursor[node] + 1));
    if (lane == 0) g_dinv[node] = d;
    float v = g_h1[node * F_H + lane];
    g_h1h[node * F_H + lane] = __float2half_rn(d * v);
}

// Layer-1 aggregation (fp16 gather, shfl-broadcast indices) + tanh + fused 32->3:
// one warp per node, lane = feature  (R8 form — verified 55.3us, occ 82%)
__global__ void __launch_bounds__(256) k_agg1(const float* __restrict__ W2) {
    __shared__ float sW[F_H * 3];
    if (threadIdx.x < F_H * 3) sW[threadIdx.x] = W2[threadIdx.x];
    __syncthreads();
    int node = (blockIdx.x * blockDim.x + threadIdx.x) >> 5;
    int lane = threadIdx.x & 31;
    if (node >= N_NODES) return;
    int deg = g_cursor[node]; if (deg > CAP) deg = CAP;
    const int* rows = g_rows + node * CAP;
    float dn = g_dinv[node];
    float acc = __half2float(g_h1h[node * F_H + lane]);   // self loop (dinv-scaled)

    for (int base = 0; base < deg; base += 32) {
        int idx = base + lane;
        int myr = (idx < deg) ? rows[idx] : 0;            // 1 coalesced load / 32 edges
        int n = deg - base; if (n > 32) n = 32;
        int j = 0;
        for (; j + 4 <= n; j += 4) {
            int r0 = __shfl_sync(0xffffffffu, myr, j + 0);
            int r1 = __shfl_sync(0xffffffffu, myr, j + 1);
            int r2 = __shfl_sync(0xffffffffu, myr, j + 2);
            int r3 = __shfl_sync(0xffffffffu, myr, j + 3);
            float v0 = __half2float(g_h1h[r0 * F_H + lane]);
            float v1 = __half2float(g_h1h[r1 * F_H + lane]);
            float v2 = __half2float(g_h1h[r2 * F_H + lane]);
            float v3 = __half2float(g_h1h[r3 * F_H + lane]);
            acc += (v0 + v1) + (v2 + v3);
        }
        for (; j < n; j++) {
            int r = __shfl_sync(0xffffffffu, myr, j);
            acc += __half2float(g_h1h[r * F_H + lane]);
        }
    }
    float a1v = tanhf(acc * dn);

    // fused projection: h2[node][j] = dinv[node] * sum_lane a1v * W2[lane][j]
    float s0 = a1v * sW[lane * 3 + 0];
    float s1 = a1v * sW[lane * 3 + 1];
    float s2 = a1v * sW[lane * 3 + 2];
#pragma unroll
    for (int d = 16; d > 0; d >>= 1) {
        s0 += __shfl_down_sync(0xffffffffu, s0, d);
        s1 += __shfl_down_sync(0xffffffffu, s1, d);
        s2 += __shfl_down_sync(0xffffffffu, s2, d);
    }
    if (lane == 0)
        g_h2[node] = make_float4(dn * s0, dn * s1, dn * s2, 0.f);
}

// Layer-2 aggregation: one warp per node, lanes stride over edges, warp reduce
__global__ void __launch_bounds__(256) k_agg2(float* __restrict__ out) {
    int node = (blockIdx.x * blockDim.x + threadIdx.x) >> 5;
    int lane = threadIdx.x & 31;
    if (node >= N_NODES) return;
    int deg = g_cursor[node]; if (deg > CAP) deg = CAP;
    const int* rows = g_rows + node * CAP;
    float s0 = 0.f, s1 = 0.f, s2 = 0.f;
    for (int e = lane; e < deg; e += 32) {
        float4 h = g_h2[rows[e]];
        s0 += h.x; s1 += h.y; s2 += h.z;
    }
#pragma unroll
    for (int d = 16; d > 0; d >>= 1) {
        s0 += __shfl_down_sync(0xffffffffu, s0, d);
        s1 += __shfl_down_sync(0xffffffffu, s1, d);
        s2 += __shfl_down_sync(0xffffffffu, s2, d);
    }
    if (lane == 0) {
        float dc = g_dinv[node];
        float4 h = g_h2[node];   // self loop (already dinv-scaled)
        out[node * 3 + 0] = dc * (s0 + h.x);
        out[node * 3 + 1] = dc * (s1 + h.y);
        out[node * 3 + 2] = dc * (s2 + h.z);
    }
}

// ---------------- launcher ----------------
extern "C" void kernel_launch(void* const* d_in, const int* in_sizes, int n_in,
                              void* d_out, int out_size) {
    const float* x  = (const float*)d_in[0];
    const void*  ei = d_in[1];                 // [2, E] int32 or int64 (runtime-detected)
    const float* W1 = (const float*)d_in[2];
    const float* W2 = (const float*)d_in[3];
    float* out = (float*)d_out;

    k_init<<<(N_NODES + 255) / 256, 256>>>((const int*)ei);
    k_fused<<<FUSED_BLOCKS, 256>>>(x, W1, ei);      // tiled GEMM + 2-edge/thread CSR
    k_dinvscale<<<(N_NODES + 7) / 8, 256>>>();      // dinv + fp16 pre-scaled h1
    k_agg1<<<(N_NODES + 7) / 8, 256>>>(W2);         // warp per node, fused h2 (R8 form)
    k_agg2<<<(N_NODES + 7) / 8, 256>>>(out);        // warp per node
}

// round 13
// speedup vs baseline: 1.2244x; 1.1047x over previous
#include <cuda_runtime.h>
#include <cuda_fp16.h>

#define N_NODES 100000
#define N_EDGES 3200000
#define F_IN 128
#define F_H 32
#define CAP 128                              // bucket capacity (P(deg>=128) ~ 1e-40)

#define H1_BLOCKS  (N_NODES / 32)            // 3125: 32 rows per block
#define CSR_BLOCKS (N_EDGES / 512)           // 6250: 2 edges/thread, 256 thr/block
#define FUSED_BLOCKS (H1_BLOCKS + CSR_BLOCKS) // 9375 = 3 * 3125 exactly

// ---------------- scratch (static device globals; no allocation) ----------------
__device__ int    g_is64;                    // edge_index dtype flag
__device__ int    g_cursor[N_NODES];         // real in-degree (excl. self loop)
__device__ float  g_dinv[N_NODES];           // (deg+1)^{-1/2}
__device__ int    g_rows[N_NODES * CAP];     // padded CSR: sources for node c at c*CAP
__device__ __align__(16) float  g_h1[N_NODES * F_H];    // RAW x @ W1 (fp32)
__device__ __align__(16) __half g_h1h[N_NODES * F_H];   // dinv[r] * h1[r], fp16
__device__ float4 g_h2[N_NODES];             // dinv[c] * (tanh(agg1) @ W2)[c], padded

// ---------------- kernels ----------------

// zero cursors; thread 0 detects int32 vs int64 edge_index
// (int64 values < 2^31 have all odd 32-bit words == 0; random int32 essentially never does)
__global__ void k_init(const int* __restrict__ ei_words) {
    int i = blockIdx.x * blockDim.x + threadIdx.x;
    if (i < N_NODES) g_cursor[i] = 0;
    if (i == 0) {
        int all_odd_zero = 1;
        for (int w = 1; w < 16; w += 2)
            if (ei_words[w] != 0) all_odd_zero = 0;
        g_is64 = all_odd_zero;
    }
}

// FUSED + CHECKERBOARDED (mod 3): block b%3==0 -> GEMM tile b/3 (0..3124);
// else CSR chunk (b/3)*2 + b%3 - 1 (0..6249). Every resident wave carries
// ~1/3 GEMM (FMA/LDS pipes) + ~2/3 CSR (LSU/atomic pipes) so the two halves
// overlap instead of running in phase-separated waves.
__global__ void __launch_bounds__(256) k_fused(const float* __restrict__ x,
                                               const float* __restrict__ W1,
                                               const void* __restrict__ ei) {
    int g = blockIdx.x / 3;
    int r3 = blockIdx.x - g * 3;
    if (r3 == 0) {
        // ---- GEMM: block computes rows [g*32, g*32+32) x all 32 cols.
        __shared__ float sx[32 * F_IN];        // 16 KB, x tile (row-major)
        __shared__ float sWT[F_H * (F_IN + 4)];// 16.9 KB, W1 transposed: sWT[col][k]
        int tid = threadIdx.x;
        int row0 = g * 32;

        const float4* x4 = (const float4*)(x + (size_t)row0 * F_IN);
        float4* sx4 = (float4*)sx;
#pragma unroll
        for (int i = 0; i < 4; i++)
            sx4[i * 256 + tid] = x4[i * 256 + tid];

#pragma unroll
        for (int i = 0; i < 16; i++) {
            int idx = i * 256 + tid;           // 0..4095
            int k = idx >> 5, col = idx & 31;
            sWT[col * (F_IN + 4) + k] = W1[idx];
        }
        __syncthreads();

        int warp = tid >> 5, lane = tid & 31;  // warp handles 4 rows, lane = out col
        int r0 = warp * 4;
        const float4* wt4 = (const float4*)(sWT + lane * (F_IN + 4));
        const float4* xr0 = (const float4*)(sx + (r0 + 0) * F_IN);
        const float4* xr1 = (const float4*)(sx + (r0 + 1) * F_IN);
        const float4* xr2 = (const float4*)(sx + (r0 + 2) * F_IN);
        const float4* xr3 = (const float4*)(sx + (r0 + 3) * F_IN);
        float a0 = 0.f, a1 = 0.f, a2 = 0.f, a3 = 0.f;
#pragma unroll
        for (int k4 = 0; k4 < 32; k4++) {
            float4 wv = wt4[k4];
            float4 v0 = xr0[k4];
            float4 v1 = xr1[k4];
            float4 v2 = xr2[k4];
            float4 v3 = xr3[k4];
            a0 += v0.x * wv.x + v0.y * wv.y + v0.z * wv.z + v0.w * wv.w;
            a1 += v1.x * wv.x + v1.y * wv.y + v1.z * wv.z + v1.w * wv.w;
            a2 += v2.x * wv.x + v2.y * wv.y + v2.z * wv.z + v2.w * wv.w;
            a3 += v3.x * wv.x + v3.y * wv.y + v3.z * wv.z + v3.w * wv.w;
        }
        int ob = (row0 + r0) * F_H + lane;
        g_h1[ob + 0 * F_H] = a0;
        g_h1[ob + 1 * F_H] = a1;
        g_h1[ob + 2 * F_H] = a2;
        g_h1[ob + 3 * F_H] = a3;
    } else {
        // ---- CSR part: 2 edges per thread, vectorized loads
        int cb = g * 2 + (r3 - 1);             // 0..6249
        int t = cb * 256 + threadIdx.x;        // 0..N_EDGES/2-1
        int r0, r1, c0, c1;
        if (g_is64) {
            const longlong2* pr = (const longlong2*)ei;
            const longlong2* pc = (const longlong2*)((const long long*)ei + N_EDGES);
            longlong2 rr = pr[t], cc = pc[t];
            r0 = (int)rr.x; r1 = (int)rr.y; c0 = (int)cc.x; c1 = (int)cc.y;
        } else {
            const int2* pr = (const int2*)ei;
            const int2* pc = (const int2*)((const int*)ei + N_EDGES);
            int2 rr = pr[t], cc = pc[t];
            r0 = rr.x; r1 = rr.y; c0 = cc.x; c1 = cc.y;
        }
        int p0 = atomicAdd(&g_cursor[c0], 1);
        if (p0 < CAP) g_rows[c0 * CAP + p0] = r0;
        int p1 = atomicAdd(&g_cursor[c1], 1);
        if (p1 < CAP) g_rows[c1 * CAP + p1] = r1;
    }
}

// dinv + fp16 scale: one warp per node; writes g_dinv and g_h1h = dinv*h1 (fp16)
__global__ void __launch_bounds__(256) k_dinvscale() {
    int node = (blockIdx.x * blockDim.x + threadIdx.x) >> 5;
    int lane = threadIdx.x & 31;
    if (node >= N_NODES) return;
    float d = rsqrtf((float)(g_cursor[node] + 1));
    if (lane == 0) g_dinv[node] = d;
    float v = g_h1[node * F_H + lane];
    g_h1h[node * F_H + lane] = __float2half_rn(d * v);
}

// Layer-1 aggregation (fp16 gather, shfl-broadcast indices) + tanh + fused 32->3:
// one warp per node, lane = feature. Fixed-trip unrolled fast path for full
// 32-edge chunks; dynamic tail only for the last partial chunk.
__global__ void __launch_bounds__(256) k_agg1(const float* __restrict__ W2) {
    __shared__ float sW[F_H * 3];
    if (threadIdx.x < F_H * 3) sW[threadIdx.x] = W2[threadIdx.x];
    __syncthreads();
    int node = (blockIdx.x * blockDim.x + threadIdx.x) >> 5;
    int lane = threadIdx.x & 31;
    if (node >= N_NODES) return;
    int deg = g_cursor[node]; if (deg > CAP) deg = CAP;
    const int* rows = g_rows + node * CAP;
    float dn = g_dinv[node];
    float acc = __half2float(g_h1h[node * F_H + lane]);   // self loop (dinv-scaled)

    int full = deg & ~31;
    for (int base = 0; base < full; base += 32) {
        int myr = rows[base + lane];                      // 1 coalesced load / 32 edges
#pragma unroll
        for (int j = 0; j < 32; j += 4) {
            int r0 = __shfl_sync(0xffffffffu, myr, j + 0);
            int r1 = __shfl_sync(0xffffffffu, myr, j + 1);
            int r2 = __shfl_sync(0xffffffffu, myr, j + 2);
            int r3 = __shfl_sync(0xffffffffu, myr, j + 3);
            float v0 = __half2float(g_h1h[r0 * F_H + lane]);
            float v1 = __half2float(g_h1h[r1 * F_H + lane]);
            float v2 = __half2float(g_h1h[r2 * F_H + lane]);
            float v3 = __half2float(g_h1h[r3 * F_H + lane]);
            acc += (v0 + v1) + (v2 + v3);
        }
    }
    int n = deg - full;
    if (n > 0) {
        int idx = full + lane;
        int myr = (idx < deg) ? rows[idx] : 0;
        int j = 0;
        for (; j + 4 <= n; j += 4) {
            int r0 = __shfl_sync(0xffffffffu, myr, j + 0);
            int r1 = __shfl_sync(0xffffffffu, myr, j + 1);
            int r2 = __shfl_sync(0xffffffffu, myr, j + 2);
            int r3 = __shfl_sync(0xffffffffu, myr, j + 3);
            float v0 = __half2float(g_h1h[r0 * F_H + lane]);
            float v1 = __half2float(g_h1h[r1 * F_H + lane]);
            float v2 = __half2float(g_h1h[r2 * F_H + lane]);
            float v3 = __half2float(g_h1h[r3 * F_H + lane]);
            acc += (v0 + v1) + (v2 + v3);
        }
        for (; j < n; j++) {
            int r = __shfl_sync(0xffffffffu, myr, j);
            acc += __half2float(g_h1h[r * F_H + lane]);
        }
    }
    float a1v = tanhf(acc * dn);

    // fused projection: h2[node][j] = dinv[node] * sum_lane a1v * W2[lane][j]
    float s0 = a1v * sW[lane * 3 + 0];
    float s1 = a1v * sW[lane * 3 + 1];
    float s2 = a1v * sW[lane * 3 + 2];
#pragma unroll
    for (int d = 16; d > 0; d >>= 1) {
        s0 += __shfl_down_sync(0xffffffffu, s0, d);
        s1 += __shfl_down_sync(0xffffffffu, s1, d);
        s2 += __shfl_down_sync(0xffffffffu, s2, d);
    }
    if (lane == 0)
        g_h2[node] = make_float4(dn * s0, dn * s1, dn * s2, 0.f);
}

// Layer-2 aggregation: one warp per node, lanes stride over edges, warp reduce
__global__ void __launch_bounds__(256) k_agg2(float* __restrict__ out) {
    int node = (blockIdx.x * blockDim.x + threadIdx.x) >> 5;
    int lane = threadIdx.x & 31;
    if (node >= N_NODES) return;
    int deg = g_cursor[node]; if (deg > CAP) deg = CAP;
    const int* rows = g_rows + node * CAP;
    float s0 = 0.f, s1 = 0.f, s2 = 0.f;
    for (int e = lane; e < deg; e += 32) {
        float4 h = g_h2[rows[e]];
        s0 += h.x; s1 += h.y; s2 += h.z;
    }
#pragma unroll
    for (int d = 16; d > 0; d >>= 1) {
        s0 += __shfl_down_sync(0xffffffffu, s0, d);
        s1 += __shfl_down_sync(0xffffffffu, s1, d);
        s2 += __shfl_down_sync(0xffffffffu, s2, d);
    }
    if (lane == 0) {
        float dc = g_dinv[node];
        float4 h = g_h2[node];   // self loop (already dinv-scaled)
        out[node * 3 + 0] = dc * (s0 + h.x);
        out[node * 3 + 1] = dc * (s1 + h.y);
        out[node * 3 + 2] = dc * (s2 + h.z);
    }
}

// ---------------- launcher ----------------
extern "C" void kernel_launch(void* const* d_in, const int* in_sizes, int n_in,
                              void* d_out, int out_size) {
    const float* x  = (const float*)d_in[0];
    const void*  ei = d_in[1];                 // [2, E] int32 or int64 (runtime-detected)
    const float* W1 = (const float*)d_in[2];
    const float* W2 = (const float*)d_in[3];
    float* out = (float*)d_out;

    k_init<<<(N_NODES + 255) / 256, 256>>>((const int*)ei);
    k_fused<<<FUSED_BLOCKS, 256>>>(x, W1, ei);      // mod-3 checkerboard GEMM + CSR
    k_dinvscale<<<(N_NODES + 7) / 8, 256>>>();      // dinv + fp16 pre-scaled h1
    k_agg1<<<(N_NODES + 7) / 8, 256>>>(W2);         // warp per node, fused h2
    k_agg2<<<(N_NODES + 7) / 8, 256>>>(out);        // warp per node
}